// round 7
// baseline (speedup 1.0000x reference)
#include <cuda_runtime.h>
#include <cstdint>
#include <cfloat>

typedef unsigned long long u64;

// Problem constants
#define Bz 16
#define Cz 64
#define Nz 4096
#define Qz 8
#define Kz 8192
#define BNz (Bz*Nz)          // 65536 points
#define TM 64                // points per block
#define TN 128               // codes per tile
#define NTILES (Kz/TN)       // 64
#define NBLK (BNz/TM)        // 1024 blocks per quantizer step

// Scratch (no allocations allowed)
__device__ float g_res[BNz*Cz];          // residual, [point][c], 16 MB
__device__ float g_cbsq[Qz*Kz];          // |cb|^2 per code
__device__ float g_losspart[Qz*NBLK];    // per-block loss partials

// ---------------- f32x2 helpers (base sm_100+ ISA, not 'a'-gated) -----------
static __device__ __forceinline__ u64 dup_f(float v) {
    u64 r; uint32_t b = __float_as_uint(v);
    asm("mov.b64 %0, {%1, %1};" : "=l"(r) : "r"(b));
    return r;
}
static __device__ __forceinline__ void ffma2_acc(u64& acc, u64 a, u64 b) {
    asm("fma.rn.f32x2 %0, %1, %2, %0;" : "+l"(acc) : "l"(a), "l"(b));
}
static __device__ __forceinline__ u64 ffma2(u64 a, u64 b, u64 c) {
    u64 d;
    asm("fma.rn.f32x2 %0, %1, %2, %3;" : "=l"(d) : "l"(a), "l"(b), "l"(c));
    return d;
}
static __device__ __forceinline__ float2 unpk(u64 v) {
    uint32_t lo, hi;
    asm("mov.b64 {%0, %1}, %2;" : "=r"(lo), "=r"(hi) : "l"(v));
    float2 f; f.x = __uint_as_float(lo); f.y = __uint_as_float(hi);
    return f;
}

// ---------------------------------------------------------------------------
__global__ void cbsq_kernel(const float* __restrict__ cb) {
    int i = blockIdx.x * blockDim.x + threadIdx.x;   // q*K + k
    if (i >= Qz*Kz) return;
    const float4* row = (const float4*)(cb + (size_t)i * Cz);
    float s = 0.f;
#pragma unroll
    for (int j = 0; j < Cz/4; ++j) {
        float4 v = row[j];
        s += v.x*v.x + v.y*v.y + v.z*v.z + v.w*v.w;
    }
    g_cbsq[i] = s;
}

__global__ void init_kernel(const float* __restrict__ x) {
    int i = blockIdx.x * blockDim.x + threadIdx.x;   // p*C + c
    if (i >= BNz*Cz) return;
    int p = i >> 6, c = i & 63;
    int b = p >> 12, n = p & (Nz - 1);
    g_res[i] = x[((size_t)b * Cz + c) * Nz + n];
}

// ---------------------------------------------------------------------------
// One RVQ step. Distance GEMM uses packed fma.rn.f32x2 (FFMA2): pairs over
// the code dimension loaded straight from smem as ulonglong2; residual value
// lane-duplicated with one MOV (alu pipe). Per-lane arithmetic identical to
// the scalar version -> bit-identical results.
__global__ void __launch_bounds__(128, 4) rvq_step(
    const float* __restrict__ cb,      // this quantizer's codebook [K][C]
    int q,
    float* __restrict__ out_idx)       // may be null
{
    __shared__ float s_resT[Cz][TM];   // residual tile, transposed  (16 KB)
    __shared__ float s_cb[Cz][TN];     // code tile, transposed      (32 KB)

    const int tid = threadIdx.x;
    const int tx  = tid & 15;          // code-group  (16)
    const int ty  = tid >> 4;          // point-group (8)
    const int pbase = blockIdx.x * TM;

    const float* cbsq = g_cbsq + (size_t)q * Kz;
    const u64 m2 = dup_f(-2.0f);

    // ---- load residual tile (transpose into smem). 2 threads per point row.
    {
        int p  = tid & 63;
        int ch = tid >> 6;             // 0/1 -> covers c 0..31 / 32..63
        const float4* src = (const float4*)(g_res + ((size_t)(pbase + p)) * Cz + ch * 32);
#pragma unroll
        for (int i = 0; i < 4; ++i) {
            float4 v0 = src[2*i], v1 = src[2*i + 1];
            int c0 = ch * 32 + i * 8;
            s_resT[c0+0][p] = v0.x; s_resT[c0+1][p] = v0.y;
            s_resT[c0+2][p] = v0.z; s_resT[c0+3][p] = v0.w;
            s_resT[c0+4][p] = v1.x; s_resT[c0+5][p] = v1.y;
            s_resT[c0+6][p] = v1.z; s_resT[c0+7][p] = v1.w;
        }
    }

    float bestd[8];
    int   bestk[8];
#pragma unroll
    for (int i = 0; i < 8; ++i) { bestd[i] = FLT_MAX; bestk[i] = 0; }

    for (int t = 0; t < NTILES; ++t) {
        const int kbase = t * TN;
        __syncthreads();   // previous tile fully consumed before overwrite
        // ---- load code tile transposed: thread owns code row kl = tid
        {
            const float4* src = (const float4*)(cb + (size_t)(kbase + tid) * Cz);
#pragma unroll
            for (int i = 0; i < 8; ++i) {
                float4 v0 = src[2*i], v1 = src[2*i + 1];
                int c0 = i * 8;
                s_cb[c0+0][tid] = v0.x; s_cb[c0+1][tid] = v0.y;
                s_cb[c0+2][tid] = v0.z; s_cb[c0+3][tid] = v0.w;
                s_cb[c0+4][tid] = v1.x; s_cb[c0+5][tid] = v1.y;
                s_cb[c0+6][tid] = v1.z; s_cb[c0+7][tid] = v1.w;
            }
        }
        __syncthreads();

        // ---- 8 points x 4 code-pairs, packed f32x2 accumulators
        u64 acc[8][4];
#pragma unroll
        for (int i = 0; i < 8; ++i)
#pragma unroll
            for (int j = 0; j < 4; ++j) acc[i][j] = 0ull;

#pragma unroll 2
        for (int c = 0; c < Cz; ++c) {
            float4 r0 = *(const float4*)&s_resT[c][ty * 8];
            float4 r1 = *(const float4*)&s_resT[c][ty * 8 + 4];
            ulonglong2 ca = *(const ulonglong2*)&s_cb[c][tx * 8];
            ulonglong2 cbp = *(const ulonglong2*)&s_cb[c][tx * 8 + 4];
            u64 cv[4] = {ca.x, ca.y, cbp.x, cbp.y};
            float rv[8] = {r0.x, r0.y, r0.z, r0.w, r1.x, r1.y, r1.z, r1.w};
#pragma unroll
            for (int i = 0; i < 8; ++i) {
                u64 ri = dup_f(rv[i]);
#pragma unroll
                for (int j = 0; j < 4; ++j)
                    ffma2_acc(acc[i][j], ri, cv[j]);
            }
        }

        // ---- dist = |cb|^2 - 2*dot (packed), running argmin (tie -> low k)
        const ulonglong2* cq = (const ulonglong2*)&cbsq[kbase + tx * 8];
        ulonglong2 q0 = cq[0], q1 = cq[1];
        u64 cbs2[4] = {q0.x, q0.y, q1.x, q1.y};
#pragma unroll
        for (int i = 0; i < 8; ++i) {
#pragma unroll
            for (int j = 0; j < 4; ++j) {
                float2 d = unpk(ffma2(m2, acc[i][j], cbs2[j]));
                int k0 = kbase + tx * 8 + j * 2;
                if (d.x < bestd[i] || (d.x == bestd[i] && k0 < bestk[i])) {
                    bestd[i] = d.x; bestk[i] = k0;
                }
                if (d.y < bestd[i] || (d.y == bestd[i] && k0 + 1 < bestk[i])) {
                    bestd[i] = d.y; bestk[i] = k0 + 1;
                }
            }
        }
    }

    // ---- reduce across the 16 tx-threads (xor butterfly stays in ty-half)
#pragma unroll
    for (int off = 1; off < 16; off <<= 1) {
#pragma unroll
        for (int i = 0; i < 8; ++i) {
            float od = __shfl_xor_sync(0xffffffffu, bestd[i], off);
            int   ok = __shfl_xor_sync(0xffffffffu, bestk[i], off);
            if (od < bestd[i] || (od == bestd[i] && ok < bestk[i])) {
                bestd[i] = od; bestk[i] = ok;
            }
        }
    }

    __syncthreads();                       // all tile reads done; reuse s_cb space
    int*   s_k = (int*)&s_cb[0][0];        // 64 ints
    float* s_l = &s_cb[2][0];              // 4 floats for warp partials
    if (tx == 0) {
#pragma unroll
        for (int i = 0; i < 8; ++i) s_k[ty * 8 + i] = bestk[i];
    }
    __syncthreads();

    // ---- fused residual update + loss partial
    float lsum = 0.f;
#pragma unroll
    for (int e0 = 0; e0 < TM * Cz; e0 += 128) {
        int e = e0 + tid;
        int p = e >> 6, c = e & 63;
        float code = cb[(size_t)s_k[p] * Cz + c];
        float rnew = g_res[(size_t)pbase * Cz + e] - code;
        g_res[(size_t)pbase * Cz + e] = rnew;
        lsum += rnew * rnew;
    }
#pragma unroll
    for (int off = 16; off > 0; off >>= 1)
        lsum += __shfl_xor_sync(0xffffffffu, lsum, off);
    if ((tid & 31) == 0) s_l[tid >> 5] = lsum;
    __syncthreads();
    if (tid == 0)
        g_losspart[q * NBLK + blockIdx.x] = s_l[0] + s_l[1] + s_l[2] + s_l[3];

    if (out_idx != nullptr && tid < TM)
        out_idx[(size_t)(pbase + tid) * Qz + q] = (float)s_k[tid];
}

// ---------------------------------------------------------------------------
// quantized = x - final residual, back in [B, C, N] layout
__global__ void final_kernel(const float* __restrict__ x, float* __restrict__ out) {
    int i = blockIdx.x * blockDim.x + threadIdx.x;
    if (i >= Bz*Cz*Nz) return;
    int n = i & (Nz - 1);
    int c = (i >> 12) & 63;
    int b = i >> 18;
    int p = (b << 12) | n;
    out[i] = x[i] - g_res[(size_t)p * Cz + c];
}

// mean loss: deterministic single-block reduction over Q*NBLK partials
__global__ void loss_kernel(float* __restrict__ out_loss) {
    __shared__ float sm[256];
    float s = 0.f;
    for (int i = threadIdx.x; i < Qz * NBLK; i += 256) s += g_losspart[i];
    sm[threadIdx.x] = s;
    __syncthreads();
    for (int w = 128; w > 0; w >>= 1) {
        if (threadIdx.x < w) sm[threadIdx.x] += sm[threadIdx.x + w];
        __syncthreads();
    }
    if (threadIdx.x == 0)
        *out_loss = sm[0] / ((float)Qz * (float)BNz * (float)Cz);
}

// ---------------------------------------------------------------------------
extern "C" void kernel_launch(void* const* d_in, const int* in_sizes, int n_in,
                              void* d_out, int out_size) {
    const float* x  = (const float*)d_in[0];   // [B, C, N]
    const float* cb = (const float*)d_in[1];   // [Q, K, C]
    float* out = (float*)d_out;

    const int OUTQ = Bz * Cz * Nz;                       // 4,194,304
    const bool full = out_size >= OUTQ + BNz * Qz + 1;   // quantized + indices + loss
    float* idx_out  = full ? out + OUTQ : nullptr;
    float* loss_out = full ? out + OUTQ + BNz * Qz : nullptr;

    cbsq_kernel<<<(Qz*Kz + 255) / 256, 256>>>(cb);
    init_kernel<<<(BNz*Cz + 255) / 256, 256>>>(x);
    for (int q = 0; q < Qz; ++q)
        rvq_step<<<NBLK, 128>>>(cb + (size_t)q * Kz * Cz, q, idx_out);
    final_kernel<<<(OUTQ + 255) / 256, 256>>>(x, out);
    if (full) loss_kernel<<<1, 256>>>(loss_out);
}

// round 9
// speedup vs baseline: 1.2745x; 1.2745x over previous
#include <cuda_runtime.h>
#include <cstdint>
#include <cfloat>

// Problem constants
#define Bz 16
#define Cz 64
#define Nz 4096
#define Qz 8
#define Kz 8192
#define BNz (Bz*Nz)          // 65536 points
#define TM 64                // points per block
#define TN 256               // codes per tile
#define NTILES (Kz/TN)       // 32
#define NBLK (BNz/TM)        // 1024 blocks per quantizer step

// Scratch (no allocations allowed)
__device__ float g_res[BNz*Cz];          // residual, [point][c], 16 MB
__device__ float g_cbT[Qz*Cz*Kz];        // codebook transposed [q][c][k], 16 MB
__device__ float g_cbsq[Qz*Kz];          // |cb|^2 per code
__device__ float g_losspart[Qz*NBLK];    // per-block loss partials

// ---------------------------------------------------------------------------
__global__ void cbsq_kernel(const float* __restrict__ cb) {
    int i = blockIdx.x * blockDim.x + threadIdx.x;   // q*K + k
    if (i >= Qz*Kz) return;
    const float4* row = (const float4*)(cb + (size_t)i * Cz);
    float s = 0.f;
#pragma unroll
    for (int j = 0; j < Cz/4; ++j) {
        float4 v = row[j];
        s += v.x*v.x + v.y*v.y + v.z*v.z + v.w*v.w;
    }
    g_cbsq[i] = s;
}

// codebook transpose: [q][k][c] -> [q][c][k]   (32x32 smem tiles)
__global__ void transpose_cb_kernel(const float* __restrict__ cb) {
    __shared__ float sm[32][33];
    const int q  = blockIdx.z;
    const int kt = blockIdx.x * 32;
    const int ct = blockIdx.y * 32;
    const float* src = cb + (size_t)q * Kz * Cz;
    float* dst = g_cbT + (size_t)q * Cz * Kz;
#pragma unroll
    for (int j = 0; j < 4; ++j) {
        int k = kt + threadIdx.y + j * 8;
        sm[threadIdx.y + j * 8][threadIdx.x] = src[(size_t)k * Cz + ct + threadIdx.x];
    }
    __syncthreads();
#pragma unroll
    for (int j = 0; j < 4; ++j) {
        int c = ct + threadIdx.y + j * 8;
        dst[(size_t)c * Kz + kt + threadIdx.x] = sm[threadIdx.x][threadIdx.y + j * 8];
    }
}

// residual := x transposed to point-major [B*N, C]
__global__ void init_kernel(const float* __restrict__ x) {
    int i = blockIdx.x * blockDim.x + threadIdx.x;   // p*C + c
    if (i >= BNz*Cz) return;
    int p = i >> 6, c = i & 63;
    int b = p >> 12, n = p & (Nz - 1);
    g_res[i] = x[((size_t)b * Cz + c) * Nz + n];
}

// ---------------------------------------------------------------------------
// One RVQ step. 8 points x 16 codes register tile (acc = 128 regs),
// 0.75 smem-bytes per FMA. Codebook tiles come from the pre-transposed
// g_cbT so fills are LDG.128 -> STS.128 (no scalar stores).
__global__ void __launch_bounds__(128, 2) rvq_step(
    const float* __restrict__ cb,      // this quantizer's codebook [K][C] (for epilogue)
    const float* __restrict__ cbT,     // this quantizer's codebook [C][K]
    int q,
    float* __restrict__ out_idx)       // may be null
{
    __shared__ float s_resT[Cz][TM];   // residual tile, transposed  (16 KB)
    __shared__ float s_cb[Cz][TN];     // code tile, c-major          (64 KB)

    const int tid = threadIdx.x;
    const int tx  = tid & 15;          // code-group  (16) -> codes j*64 + tx*4 + e
    const int ty  = tid >> 4;          // point-group (8)  -> points ty*8 + i
    const int pbase = blockIdx.x * TM;

    const float* cbsq = g_cbsq + (size_t)q * Kz;

    // ---- load residual tile (transpose into smem). 2 threads per point row.
    {
        int p  = tid & 63;
        int ch = tid >> 6;             // 0/1 -> covers c 0..31 / 32..63
        const float4* src = (const float4*)(g_res + ((size_t)(pbase + p)) * Cz + ch * 32);
#pragma unroll
        for (int i = 0; i < 4; ++i) {
            float4 v0 = src[2*i], v1 = src[2*i + 1];
            int c0 = ch * 32 + i * 8;
            s_resT[c0+0][p] = v0.x; s_resT[c0+1][p] = v0.y;
            s_resT[c0+2][p] = v0.z; s_resT[c0+3][p] = v0.w;
            s_resT[c0+4][p] = v1.x; s_resT[c0+5][p] = v1.y;
            s_resT[c0+6][p] = v1.z; s_resT[c0+7][p] = v1.w;
        }
    }

    float bestd[8];
    int   bestk[8];
#pragma unroll
    for (int i = 0; i < 8; ++i) { bestd[i] = FLT_MAX; bestk[i] = 0; }

    for (int t = 0; t < NTILES; ++t) {
        const int kbase = t * TN;
        __syncthreads();   // previous tile fully consumed before overwrite
        // ---- fill code tile from transposed codebook: fully vectorized
        {
            const float4* src = (const float4*)(cbT + kbase);   // row stride Kz/4 f4
            float4* dst = (float4*)&s_cb[0][0];
#pragma unroll
            for (int i = 0; i < 32; ++i) {
                int f = i * 128 + tid;         // 4096 float4 per tile
                int row = f >> 6, col4 = f & 63;
                dst[f] = src[(size_t)row * (Kz/4) + col4];
            }
        }
        __syncthreads();

        // ---- 8 points x 16 codes register tile over c = 0..63
        float acc[8][16];
#pragma unroll
        for (int i = 0; i < 8; ++i)
#pragma unroll
            for (int j = 0; j < 16; ++j) acc[i][j] = 0.f;

#pragma unroll 2
        for (int c = 0; c < Cz; ++c) {
            float4 r0 = *(const float4*)&s_resT[c][ty * 8];
            float4 r1 = *(const float4*)&s_resT[c][ty * 8 + 4];
            float4 b0 = *(const float4*)&s_cb[c][tx * 4];
            float4 b1 = *(const float4*)&s_cb[c][64 + tx * 4];
            float4 b2 = *(const float4*)&s_cb[c][128 + tx * 4];
            float4 b3 = *(const float4*)&s_cb[c][192 + tx * 4];
            float rv[8] = {r0.x, r0.y, r0.z, r0.w, r1.x, r1.y, r1.z, r1.w};
            float cv[16] = {b0.x, b0.y, b0.z, b0.w, b1.x, b1.y, b1.z, b1.w,
                            b2.x, b2.y, b2.z, b2.w, b3.x, b3.y, b3.z, b3.w};
#pragma unroll
            for (int i = 0; i < 8; ++i)
#pragma unroll
                for (int j = 0; j < 16; ++j)
                    acc[i][j] = fmaf(rv[i], cv[j], acc[i][j]);
        }

        // ---- dist = |cb|^2 - 2*dot ; running argmin
        // Within a thread k strictly increases over (t, jg, e), so strict '<'
        // keeps the lowest tied index automatically.
        float cbs[16];
#pragma unroll
        for (int jg = 0; jg < 4; ++jg) {
            float4 v = *(const float4*)&cbsq[kbase + jg * 64 + tx * 4];
            cbs[jg*4+0] = v.x; cbs[jg*4+1] = v.y; cbs[jg*4+2] = v.z; cbs[jg*4+3] = v.w;
        }
#pragma unroll
        for (int i = 0; i < 8; ++i) {
#pragma unroll
            for (int jg = 0; jg < 4; ++jg) {
#pragma unroll
                for (int e = 0; e < 4; ++e) {
                    float d = fmaf(-2.f, acc[i][jg*4+e], cbs[jg*4+e]);
                    int   k = kbase + jg * 64 + tx * 4 + e;
                    if (d < bestd[i]) { bestd[i] = d; bestk[i] = k; }
                }
            }
        }
    }

    // ---- reduce across the 16 tx-threads (xor butterfly stays in ty-half)
#pragma unroll
    for (int off = 1; off < 16; off <<= 1) {
#pragma unroll
        for (int i = 0; i < 8; ++i) {
            float od = __shfl_xor_sync(0xffffffffu, bestd[i], off);
            int   ok = __shfl_xor_sync(0xffffffffu, bestk[i], off);
            if (od < bestd[i] || (od == bestd[i] && ok < bestk[i])) {
                bestd[i] = od; bestk[i] = ok;
            }
        }
    }

    __syncthreads();                       // all tile reads done; reuse s_cb space
    int*   s_k = (int*)&s_cb[0][0];        // 64 ints
    float* s_l = &s_cb[2][0];              // 4 floats for warp partials
    if (tx == 0) {
#pragma unroll
        for (int i = 0; i < 8; ++i) s_k[ty * 8 + i] = bestk[i];
    }
    __syncthreads();

    // ---- fused residual update + loss partial
    float lsum = 0.f;
#pragma unroll
    for (int e0 = 0; e0 < TM * Cz; e0 += 128) {
        int e = e0 + tid;
        int p = e >> 6, c = e & 63;
        float code = cb[(size_t)s_k[p] * Cz + c];
        float rnew = g_res[(size_t)pbase * Cz + e] - code;
        g_res[(size_t)pbase * Cz + e] = rnew;
        lsum += rnew * rnew;
    }
#pragma unroll
    for (int off = 16; off > 0; off >>= 1)
        lsum += __shfl_xor_sync(0xffffffffu, lsum, off);
    if ((tid & 31) == 0) s_l[tid >> 5] = lsum;
    __syncthreads();
    if (tid == 0)
        g_losspart[q * NBLK + blockIdx.x] = s_l[0] + s_l[1] + s_l[2] + s_l[3];

    if (out_idx != nullptr && tid < TM)
        out_idx[(size_t)(pbase + tid) * Qz + q] = (float)s_k[tid];
}

// ---------------------------------------------------------------------------
// quantized = x - final residual, back in [B, C, N] layout
__global__ void final_kernel(const float* __restrict__ x, float* __restrict__ out) {
    int i = blockIdx.x * blockDim.x + threadIdx.x;
    if (i >= Bz*Cz*Nz) return;
    int n = i & (Nz - 1);
    int c = (i >> 12) & 63;
    int b = i >> 18;
    int p = (b << 12) | n;
    out[i] = x[i] - g_res[(size_t)p * Cz + c];
}

// mean loss: deterministic single-block reduction over Q*NBLK partials
__global__ void loss_kernel(float* __restrict__ out_loss) {
    __shared__ float sm[256];
    float s = 0.f;
    for (int i = threadIdx.x; i < Qz * NBLK; i += 256) s += g_losspart[i];
    sm[threadIdx.x] = s;
    __syncthreads();
    for (int w = 128; w > 0; w >>= 1) {
        if (threadIdx.x < w) sm[threadIdx.x] += sm[threadIdx.x + w];
        __syncthreads();
    }
    if (threadIdx.x == 0)
        *out_loss = sm[0] / ((float)Qz * (float)BNz * (float)Cz);
}

// ---------------------------------------------------------------------------
extern "C" void kernel_launch(void* const* d_in, const int* in_sizes, int n_in,
                              void* d_out, int out_size) {
    const float* x  = (const float*)d_in[0];   // [B, C, N]
    const float* cb = (const float*)d_in[1];   // [Q, K, C]
    float* out = (float*)d_out;

    const int OUTQ = Bz * Cz * Nz;                       // 4,194,304
    const bool full = out_size >= OUTQ + BNz * Qz + 1;   // quantized + indices + loss
    float* idx_out  = full ? out + OUTQ : nullptr;
    float* loss_out = full ? out + OUTQ + BNz * Qz : nullptr;

    cbsq_kernel<<<(Qz*Kz + 255) / 256, 256>>>(cb);
    {
        dim3 g(Kz/32, Cz/32, Qz), b(32, 8);
        transpose_cb_kernel<<<g, b>>>(cb);
    }
    init_kernel<<<(BNz*Cz + 255) / 256, 256>>>(x);

    float* cbT_base;
    cudaGetSymbolAddress((void**)&cbT_base, g_cbT);
    for (int q = 0; q < Qz; ++q)
        rvq_step<<<NBLK, 128>>>(cb + (size_t)q * Kz * Cz,
                                cbT_base + (size_t)q * Cz * Kz, q, idx_out);
    final_kernel<<<(OUTQ + 255) / 256, 256>>>(x, out);
    if (full) loss_kernel<<<1, 256>>>(loss_out);
}